// round 14
// baseline (speedup 1.0000x reference)
#include <cuda_runtime.h>
#include <cuda_bf16.h>
#include <cstdint>
#include <math.h>

// ---------------------------------------------------------------------------
// Problem constants
// ---------------------------------------------------------------------------
#define N 4096
#define D 512
#define NB 151
#define HALFB 75
#define INV_STEP 75.0f
#define P_TOTAL 8386560.0   // N*(N-1)/2

#define BM 128
#define BK 64             // bf16 K per chunk = 128B rows (swizzle atom)
#define NCHUNK (D / BK)   // 8
#define NT (N / BM)       // 32
#define NTILES (NT * (NT + 1) / 2)  // 528
#define NWORK 296                   // 2 persistent CTAs per SM
#define STAGE_BYTES 32768           // 2 tiles (A,B) x 128 rows x 128B

// dynamic smem layout (main kernel)
#define OFF_CLS   0                 // 256 ints = 1024B
#define OFF_CDF   1024              // 151 float2 = 1208B -> pad 1216
#define OFF_RED   2240              // 16 x 2 floats = 128B
#define OFF_TILES 4096
#define SMEM_TOTAL (OFF_TILES + 2 * STAGE_BYTES)   // 69632

// ---------------------------------------------------------------------------
// Inline PTX helpers
// ---------------------------------------------------------------------------
__device__ __forceinline__ uint32_t smem_u32(const void* p) {
    uint32_t a;
    asm("{ .reg .u64 t; cvta.to.shared.u64 t, %1; cvt.u32.u64 %0, t; }" : "=r"(a) : "l"(p));
    return a;
}
__device__ __forceinline__ void cp16(uint32_t dst, const void* src) {
    asm volatile("cp.async.cg.shared.global [%0], [%1], 16;" :: "r"(dst), "l"(src) : "memory");
}
__device__ __forceinline__ void cp_commit() {
    asm volatile("cp.async.commit_group;" ::: "memory");
}
__device__ __forceinline__ void cp_wait0() {
    asm volatile("cp.async.wait_group 0;" ::: "memory");
}
__device__ __forceinline__ void ldmx4(uint32_t* r, uint32_t addr) {
    asm volatile("ldmatrix.sync.aligned.m8n8.x4.shared.b16 {%0,%1,%2,%3}, [%4];"
                 : "=r"(r[0]), "=r"(r[1]), "=r"(r[2]), "=r"(r[3]) : "r"(addr));
}
__device__ __forceinline__ void mma16816(float* c, const uint32_t* a, const uint32_t* b) {
    asm volatile("mma.sync.aligned.m16n8k16.row.col.f32.bf16.bf16.f32 "
                 "{%0,%1,%2,%3}, {%4,%5,%6,%7}, {%8,%9}, {%0,%1,%2,%3};"
                 : "+f"(c[0]), "+f"(c[1]), "+f"(c[2]), "+f"(c[3])
                 : "r"(a[0]), "r"(a[1]), "r"(a[2]), "r"(a[3]), "r"(b[0]), "r"(b[1]));
}

// ---------------------------------------------------------------------------
// Scratch (static device memory -- no allocations)
// ---------------------------------------------------------------------------
__device__ __nv_bfloat16 g_bf[(size_t)N * D];
__device__ float g_histpos[NB + 1];
__device__ float2 g_cdf[NB];       // (cdf[b], cdf[b+1]-cdf[b]), normalized
__device__ float g_Ppos;
__device__ double g_sumAll;
__device__ double g_sumPos;
__device__ int g_done;

// ---------------------------------------------------------------------------
// Kernel 1: warp-per-row L2-normalize into bf16; block 0 zeroes accum state
// ---------------------------------------------------------------------------
__global__ void norm_kernel(const float* __restrict__ f) {
    if (blockIdx.x == 0) {
        if (threadIdx.x == 0) { g_done = 0; g_sumAll = 0.0; g_sumPos = 0.0; }
        if (threadIdx.x < NB + 1) g_histpos[threadIdx.x] = 0.0f;
    }
    int row = blockIdx.x * 8 + (threadIdx.x >> 5);
    int lane = threadIdx.x & 31;
    const float4* src = (const float4*)(f + (size_t)row * D);
    float4 v[4];
    float ss = 0.0f;
    #pragma unroll
    for (int r = 0; r < 4; r++) {
        v[r] = src[lane + 32 * r];
        ss += v[r].x * v[r].x + v[r].y * v[r].y + v[r].z * v[r].z + v[r].w * v[r].w;
    }
    #pragma unroll
    for (int o = 16; o > 0; o >>= 1) ss += __shfl_xor_sync(0xffffffffu, ss, o);
    float inv = 1.0f / sqrtf(ss);
    uint2* dst = (uint2*)(g_bf + (size_t)row * D);
    #pragma unroll
    for (int r = 0; r < 4; r++) {
        __nv_bfloat162 p0 = __floats2bfloat162_rn(v[r].x * inv, v[r].y * inv);
        __nv_bfloat162 p1 = __floats2bfloat162_rn(v[r].z * inv, v[r].w * inv);
        dst[lane + 32 * r] = make_uint2(*(unsigned*)&p0, *(unsigned*)&p1);
    }
}

// ---------------------------------------------------------------------------
// Kernel 2: positive pairs -> hist_pos. One block per row i; threads scan j>i
// for class matches (rare: ~2 per row) and compute the bf16 dot directly.
// ---------------------------------------------------------------------------
__device__ __forceinline__ float dot8(uint4 a, uint4 b) {
    unsigned av[4] = {a.x, a.y, a.z, a.w};
    unsigned bv[4] = {b.x, b.y, b.z, b.w};
    float s = 0.0f;
    #pragma unroll
    for (int r = 0; r < 4; r++) {
        float2 fa = __bfloat1622float2(*(__nv_bfloat162*)&av[r]);
        float2 fb = __bfloat1622float2(*(__nv_bfloat162*)&bv[r]);
        s = fmaf(fa.x, fb.x, s);
        s = fmaf(fa.y, fb.y, s);
    }
    return s;
}
__global__ void pos_kernel(const int* __restrict__ classes) {
    int i = blockIdx.x;
    int ci = classes[i];
    const uint4* ri = (const uint4*)(g_bf + (size_t)i * D);   // 64 uint4 per row
    for (int j = i + 1 + threadIdx.x; j < N; j += blockDim.x) {
        if (classes[j] != ci) continue;
        const uint4* rj = (const uint4*)(g_bf + (size_t)j * D);
        float s = 0.0f;
        #pragma unroll 4
        for (int k = 0; k < 64; k++) s += dot8(ri[k], rj[k]);
        float x = s * INV_STEP;
        float kf = floorf(x);
        float fr = x - kf;
        int lo = (int)kf + HALFB;
        if (lo < 0) { lo = 0; fr = 0.0f; }
        else if (lo > NB - 2) { lo = NB - 2; fr = 1.0f; }
        atomicAdd(&g_histpos[lo], 1.0f - fr);
        atomicAdd(&g_histpos[lo + 1], fr);
    }
}

// ---------------------------------------------------------------------------
// Kernel 3: build normalized cdf table (single block, 256 threads)
// ---------------------------------------------------------------------------
__global__ void cdf_kernel() {
    __shared__ float h[NB];
    __shared__ float pref[NB];
    int t = threadIdx.x;
    if (t < NB) { h[t] = g_histpos[t]; pref[t] = h[t]; }
    __syncthreads();
    for (int off = 1; off < NB; off <<= 1) {
        float v = 0.0f;
        if (t < NB && t >= off) v = pref[t - off];
        __syncthreads();
        if (t < NB && t >= off) pref[t] += v;
        __syncthreads();
    }
    float Pp = pref[NB - 1];
    if (t == 0) g_Ppos = Pp;
    float invP = 1.0f / Pp;
    if (t < NB) {
        float d = (t < NB - 1) ? h[t + 1] * invP : 0.0f;
        g_cdf[t] = make_float2(pref[t] * invP, d);
    }
}

// ---------------------------------------------------------------------------
// decode linear upper-tri tile id -> (rowBase, colBase)
// ---------------------------------------------------------------------------
__device__ __forceinline__ void decode_tile(int t, int& rowBase, int& colBase) {
    int br = 0;
    while (t >= NT - br) { t -= NT - br; br++; }
    rowBase = br * BM;
    colBase = (br + t) * BM;
}

// ---------------------------------------------------------------------------
// Kernel 4: persistent HMMA bf16 f@f^T + cdf-lerp epilogue (NO atomics)
// 512 threads = 16 warps, warp grid 4(m) x 4(n), warp tile 32x32
// Per pair: g = cdf[lo] + fr*dcdf[lo]; accAll += g; if pos: accPos += g.
// loss = (sumAll - sumPos) / P_neg.
// ---------------------------------------------------------------------------
__global__ void __launch_bounds__(512, 2) pair_mma_loss_kernel(
        const int* __restrict__ classes, float* __restrict__ out) {
    extern __shared__ char smem[];
    uint32_t sb = smem_u32(smem);
    int tid = threadIdx.x;
    int wid = tid >> 5;
    int lane = tid & 31;

    int* clsS = (int*)(smem + OFF_CLS);
    float2* cdfS = (float2*)(smem + OFF_CDF);
    if (tid < NB) cdfS[tid] = g_cdf[tid];

    uint32_t tilesBase = sb + OFF_TILES;
    int ldr = tid >> 3;
    int ldp = tid & 7;

    int wm = wid & 3;
    int wn = wid >> 2;
    int blk = lane >> 3;
    int lrow = lane & 7;

    int tileIdx = blockIdx.x;
    int rowBase, colBase;
    decode_tile(tileIdx, rowBase, colBase);
    const char* gA = (const char*)(g_bf + (size_t)rowBase * D);
    const char* gB = (const char*)(g_bf + (size_t)colBase * D);

    // prologue: issue chunk0 of first tile into stage 0
    #pragma unroll
    for (int it = 0; it < 4; it++) {
        const int tile = it >> 1;
        int r = ((it & 1) << 6) + ldr;
        uint32_t dst = tilesBase + tile * 16384 + r * 128 + ((ldp ^ (r & 7)) << 4);
        const char* src = (tile ? gB : gA) + ((size_t)r * D + ldp * 8) * 2;
        cp16(dst, src);
    }
    cp_commit();

    float accAll = 0.0f, accPos = 0.0f;

    while (tileIdx < NTILES) {
        int nextTile = tileIdx + NWORK;
        int rowBaseN = 0, colBaseN = 0;
        const char *gAn = gA, *gBn = gB;
        if (nextTile < NTILES) {
            decode_tile(nextTile, rowBaseN, colBaseN);
            gAn = (const char*)(g_bf + (size_t)rowBaseN * D);
            gBn = (const char*)(g_bf + (size_t)colBaseN * D);
        }

        __syncthreads();   // prior epilogue done reading clsS; cdfS visible
        if (tid < 128) clsS[tid] = classes[rowBase + tid];
        else if (tid < 256) clsS[tid] = classes[colBase + tid - 128];

        float acc[2][4][4];
        #pragma unroll
        for (int mi = 0; mi < 2; mi++)
            #pragma unroll
            for (int ni = 0; ni < 4; ni++)
                #pragma unroll
                for (int q = 0; q < 4; q++) acc[mi][ni][q] = 0.0f;

        for (int c = 0; c < NCHUNK; c++) {
            cp_wait0();
            __syncthreads();
            if (c + 1 < NCHUNK) {
                uint32_t stb = tilesBase + ((c + 1) & 1) * STAGE_BYTES;
                #pragma unroll
                for (int it = 0; it < 4; it++) {
                    const int tile = it >> 1;
                    int r = ((it & 1) << 6) + ldr;
                    uint32_t dst = stb + tile * 16384 + r * 128 + ((ldp ^ (r & 7)) << 4);
                    const char* src = (tile ? gB : gA) +
                                      ((size_t)r * D + (size_t)(c + 1) * BK + ldp * 8) * 2;
                    cp16(dst, src);
                }
            } else if (nextTile < NTILES) {
                #pragma unroll
                for (int it = 0; it < 4; it++) {
                    const int tile = it >> 1;
                    int r = ((it & 1) << 6) + ldr;
                    uint32_t dst = tilesBase + tile * 16384 + r * 128 + ((ldp ^ (r & 7)) << 4);
                    const char* src = (tile ? gBn : gAn) + ((size_t)r * D + ldp * 8) * 2;
                    cp16(dst, src);
                }
            }
            cp_commit();

            uint32_t aBase = tilesBase + (c & 1) * STAGE_BYTES;
            uint32_t bBase = aBase + 16384;

            #pragma unroll
            for (int ks = 0; ks < 4; ks++) {
                uint32_t af[2][4], bfr[4][2];
                #pragma unroll
                for (int mi = 0; mi < 2; mi++) {
                    int row = wm * 32 + mi * 16 + ((blk & 1) << 3) + lrow;
                    int piece = ks * 2 + (blk >> 1);
                    ldmx4(af[mi], aBase + row * 128 + ((piece ^ (row & 7)) << 4));
                }
                #pragma unroll
                for (int ni2 = 0; ni2 < 2; ni2++) {
                    int row = wn * 32 + ni2 * 16 + ((blk >> 1) << 3) + lrow;
                    int piece = ks * 2 + (blk & 1);
                    uint32_t r4[4];
                    ldmx4(r4, bBase + row * 128 + ((piece ^ (row & 7)) << 4));
                    bfr[ni2 * 2][0] = r4[0]; bfr[ni2 * 2][1] = r4[1];
                    bfr[ni2 * 2 + 1][0] = r4[2]; bfr[ni2 * 2 + 1][1] = r4[3];
                }
                #pragma unroll
                for (int mi = 0; mi < 2; mi++)
                    #pragma unroll
                    for (int ni = 0; ni < 4; ni++)
                        mma16816(acc[mi][ni], af[mi], bfr[ni]);
            }
        }

        // ---- fused epilogue: cdf lerp, pure register accumulation ----
        int iBase = rowBase + wm * 32 + (lane >> 2);
        int jBase = colBase + wn * 32 + (lane & 3) * 2;
        const int* clsB = clsS + 128;
        bool offDiag = (rowBase != colBase);

        #pragma unroll
        for (int mi = 0; mi < 2; mi++) {
            int i0 = iBase + mi * 16;
            int ci0 = clsS[i0 - rowBase];
            int ci1 = clsS[i0 + 8 - rowBase];
            #pragma unroll
            for (int ni = 0; ni < 4; ni++) {
                int j0 = jBase + ni * 8;
                int cj0 = clsB[j0 - colBase];
                int cj1 = clsB[j0 + 1 - colBase];
                #pragma unroll
                for (int q = 0; q < 4; q++) {
                    int i = i0 + ((q >> 1) << 3);
                    int j = j0 + (q & 1);
                    if (offDiag || i < j) {
                        int ci = (q & 2) ? ci1 : ci0;
                        int cj = (q & 1) ? cj1 : cj0;
                        float x = acc[mi][ni][q] * INV_STEP;
                        float kf = floorf(x);
                        float fr = x - kf;
                        int lo = (int)kf + HALFB;
                        if (lo < 0) { lo = 0; fr = 0.0f; }
                        else if (lo > NB - 2) { lo = NB - 2; fr = 1.0f; }
                        float2 cp = cdfS[lo];
                        float g = fmaf(fr, cp.y, cp.x);
                        accAll += g;
                        if (ci == cj) accPos += g;
                    }
                }
            }
        }

        tileIdx = nextTile;
        rowBase = rowBaseN; colBase = colBaseN;
        gA = gAn; gB = gBn;
    }

    // ---- CTA reduction of the two accumulators ----
    #pragma unroll
    for (int o = 16; o > 0; o >>= 1) {
        accAll += __shfl_xor_sync(0xffffffffu, accAll, o);
        accPos += __shfl_xor_sync(0xffffffffu, accPos, o);
    }
    float* redA = (float*)(smem + OFF_RED);
    float* redP = redA + 16;
    if (lane == 0) { redA[wid] = accAll; redP[wid] = accPos; }
    __syncthreads();
    if (tid == 0) {
        float sA = 0.0f, sP = 0.0f;
        #pragma unroll
        for (int w = 0; w < 16; w++) { sA += redA[w]; sP += redP[w]; }
        atomicAdd(&g_sumAll, (double)sA);
        atomicAdd(&g_sumPos, (double)sP);
    }

    // ---- last CTA writes the loss ----
    __threadfence();
    __shared__ int isLast;
    if (tid == 0) {
        int old = atomicAdd(&g_done, 1);
        isLast = (old == NWORK - 1) ? 1 : 0;
    }
    __syncthreads();
    if (isLast && tid == 0) {
        double Pp = (double)g_Ppos;
        double Pn = P_TOTAL - Pp;
        out[0] = (float)((g_sumAll - g_sumPos) / Pn);
    }
}

// ---------------------------------------------------------------------------
extern "C" void kernel_launch(void* const* d_in, const int* in_sizes, int n_in,
                              void* d_out, int out_size) {
    const float* features = (const float*)d_in[0];
    const int*   classes  = (const int*)d_in[1];
    float*       out      = (float*)d_out;

    cudaFuncSetAttribute(pair_mma_loss_kernel,
                         cudaFuncAttributeMaxDynamicSharedMemorySize, SMEM_TOTAL);

    norm_kernel<<<512, 256>>>(features);
    pos_kernel<<<N, 256>>>(classes);
    cdf_kernel<<<1, 256>>>();
    pair_mma_loss_kernel<<<NWORK, 512, SMEM_TOTAL>>>(classes, out);
}

// round 15
// speedup vs baseline: 1.0385x; 1.0385x over previous
#include <cuda_runtime.h>
#include <cuda_bf16.h>
#include <cstdint>
#include <math.h>

// ---------------------------------------------------------------------------
// Problem constants
// ---------------------------------------------------------------------------
#define N 4096
#define D 512
#define NB 151
#define HALFB 75
#define INV_STEP 75.0f
#define P_TOTAL 8386560.0   // N*(N-1)/2

#define BM 128
#define BK 64             // bf16 K per chunk = 128B rows (swizzle atom)
#define NCHUNK (D / BK)   // 8
#define NT (N / BM)       // 32
#define NTILES (NT * (NT + 1) / 2)  // 528
#define NWORK 296                   // 2 persistent CTAs per SM
#define STAGE_BYTES 32768           // 2 tiles (A,B) x 128 rows x 128B

// dynamic smem layout (main kernel)
#define OFF_CLS   0                 // 256 ints = 1024B
#define OFF_CDF   1024              // 151 float2 = 1208B -> pad 1216
#define OFF_RED   2240              // 32 floats = 128B
#define OFF_SCAN  2368              // 152 floats = 608B
#define OFF_TILES 4096
#define SMEM_TOTAL (OFF_TILES + 2 * STAGE_BYTES)   // 69632

// ---------------------------------------------------------------------------
// Inline PTX helpers
// ---------------------------------------------------------------------------
__device__ __forceinline__ uint32_t smem_u32(const void* p) {
    uint32_t a;
    asm("{ .reg .u64 t; cvta.to.shared.u64 t, %1; cvt.u32.u64 %0, t; }" : "=r"(a) : "l"(p));
    return a;
}
__device__ __forceinline__ void cp16(uint32_t dst, const void* src) {
    asm volatile("cp.async.cg.shared.global [%0], [%1], 16;" :: "r"(dst), "l"(src) : "memory");
}
__device__ __forceinline__ void cp_commit() {
    asm volatile("cp.async.commit_group;" ::: "memory");
}
__device__ __forceinline__ void cp_wait0() {
    asm volatile("cp.async.wait_group 0;" ::: "memory");
}
__device__ __forceinline__ void ldmx4(uint32_t* r, uint32_t addr) {
    asm volatile("ldmatrix.sync.aligned.m8n8.x4.shared.b16 {%0,%1,%2,%3}, [%4];"
                 : "=r"(r[0]), "=r"(r[1]), "=r"(r[2]), "=r"(r[3]) : "r"(addr));
}
__device__ __forceinline__ void mma16816(float* c, const uint32_t* a, const uint32_t* b) {
    asm volatile("mma.sync.aligned.m16n8k16.row.col.f32.bf16.bf16.f32 "
                 "{%0,%1,%2,%3}, {%4,%5,%6,%7}, {%8,%9}, {%0,%1,%2,%3};"
                 : "+f"(c[0]), "+f"(c[1]), "+f"(c[2]), "+f"(c[3])
                 : "r"(a[0]), "r"(a[1]), "r"(a[2]), "r"(a[3]), "r"(b[0]), "r"(b[1]));
}

// ---------------------------------------------------------------------------
// Scratch (static device memory -- no allocations)
// ---------------------------------------------------------------------------
__device__ __nv_bfloat16 g_bf[(size_t)N * D];
__device__ float g_histpos[NB + 1];
__device__ double g_sumAll;
__device__ double g_sumPos;
__device__ int g_done;

// ---------------------------------------------------------------------------
// Kernel 1: warp-per-row L2-normalize into bf16; block 0 zeroes accum state
// ---------------------------------------------------------------------------
__global__ void norm_kernel(const float* __restrict__ f) {
    if (blockIdx.x == 0) {
        if (threadIdx.x == 0) { g_done = 0; g_sumAll = 0.0; g_sumPos = 0.0; }
        if (threadIdx.x < NB + 1) g_histpos[threadIdx.x] = 0.0f;
    }
    int row = blockIdx.x * 8 + (threadIdx.x >> 5);
    int lane = threadIdx.x & 31;
    const float4* src = (const float4*)(f + (size_t)row * D);
    float4 v[4];
    float ss = 0.0f;
    #pragma unroll
    for (int r = 0; r < 4; r++) {
        v[r] = src[lane + 32 * r];
        ss += v[r].x * v[r].x + v[r].y * v[r].y + v[r].z * v[r].z + v[r].w * v[r].w;
    }
    #pragma unroll
    for (int o = 16; o > 0; o >>= 1) ss += __shfl_xor_sync(0xffffffffu, ss, o);
    float inv = 1.0f / sqrtf(ss);
    uint2* dst = (uint2*)(g_bf + (size_t)row * D);
    #pragma unroll
    for (int r = 0; r < 4; r++) {
        __nv_bfloat162 p0 = __floats2bfloat162_rn(v[r].x * inv, v[r].y * inv);
        __nv_bfloat162 p1 = __floats2bfloat162_rn(v[r].z * inv, v[r].w * inv);
        dst[lane + 32 * r] = make_uint2(*(unsigned*)&p0, *(unsigned*)&p1);
    }
}

// ---------------------------------------------------------------------------
// Kernel 2: positive pairs -> hist_pos. Warp-cooperative:
// each warp strides rows i; lanes scan j in 32-wide coalesced steps; on a
// class match the whole warp computes the 512-element dot in parallel.
// ---------------------------------------------------------------------------
__device__ __forceinline__ float dot8(uint4 a, uint4 b) {
    unsigned av[4] = {a.x, a.y, a.z, a.w};
    unsigned bv[4] = {b.x, b.y, b.z, b.w};
    float s = 0.0f;
    #pragma unroll
    for (int r = 0; r < 4; r++) {
        float2 fa = __bfloat1622float2(*(__nv_bfloat162*)&av[r]);
        float2 fb = __bfloat1622float2(*(__nv_bfloat162*)&bv[r]);
        s = fmaf(fa.x, fb.x, s);
        s = fmaf(fa.y, fb.y, s);
    }
    return s;
}
__global__ void pos_kernel(const int* __restrict__ classes) {
    int wg = (blockIdx.x * blockDim.x + threadIdx.x) >> 5;
    int lane = threadIdx.x & 31;
    int nw = (gridDim.x * blockDim.x) >> 5;
    for (int i = wg; i < N; i += nw) {
        int ci = classes[i];
        const uint4* ri = (const uint4*)(g_bf + (size_t)i * D);   // 64 uint4
        uint4 a0 = ri[lane];
        uint4 a1 = ri[lane + 32];
        for (int jb = i + 1; jb < N; jb += 32) {
            int j = jb + lane;
            bool m = (j < N) && (classes[j] == ci);
            unsigned mm = __ballot_sync(0xffffffffu, m);
            while (mm) {
                int src = __ffs(mm) - 1;
                mm &= mm - 1;
                int jj = jb + src;
                const uint4* rj = (const uint4*)(g_bf + (size_t)jj * D);
                float s = dot8(a0, rj[lane]) + dot8(a1, rj[lane + 32]);
                #pragma unroll
                for (int o = 16; o > 0; o >>= 1) s += __shfl_xor_sync(0xffffffffu, s, o);
                if (lane == 0) {
                    float x = s * INV_STEP;
                    float kf = floorf(x);
                    float fr = x - kf;
                    int lo = (int)kf + HALFB;
                    if (lo < 0) { lo = 0; fr = 0.0f; }
                    else if (lo > NB - 2) { lo = NB - 2; fr = 1.0f; }
                    atomicAdd(&g_histpos[lo], 1.0f - fr);
                    atomicAdd(&g_histpos[lo + 1], fr);
                }
            }
        }
    }
}

// ---------------------------------------------------------------------------
// decode linear upper-tri tile id -> (rowBase, colBase)
// ---------------------------------------------------------------------------
__device__ __forceinline__ void decode_tile(int t, int& rowBase, int& colBase) {
    int br = 0;
    while (t >= NT - br) { t -= NT - br; br++; }
    rowBase = br * BM;
    colBase = (br + t) * BM;
}

// ---------------------------------------------------------------------------
// Kernel 3: persistent HMMA bf16 f@f^T + cdf-lerp epilogue (NO atomics)
// Builds the normalized cdf table locally from g_histpos, then runs the GEMM.
// Per pair: g = cdf[lo] + fr*dcdf[lo]; accAll += g; if pos: accPos += g.
// loss = (sumAll - sumPos) / P_neg.
// ---------------------------------------------------------------------------
__global__ void __launch_bounds__(512, 2) pair_mma_loss_kernel(
        const int* __restrict__ classes, float* __restrict__ out) {
    extern __shared__ char smem[];
    uint32_t sb = smem_u32(smem);
    int tid = threadIdx.x;
    int wid = tid >> 5;
    int lane = tid & 31;

    int* clsS = (int*)(smem + OFF_CLS);
    float2* cdfS = (float2*)(smem + OFF_CDF);
    float* scan = (float*)(smem + OFF_SCAN);

    uint32_t tilesBase = sb + OFF_TILES;
    int ldr = tid >> 3;
    int ldp = tid & 7;

    int wm = wid & 3;
    int wn = wid >> 2;
    int blk = lane >> 3;
    int lrow = lane & 7;

    int tileIdx = blockIdx.x;
    int rowBase, colBase;
    decode_tile(tileIdx, rowBase, colBase);
    const char* gA = (const char*)(g_bf + (size_t)rowBase * D);
    const char* gB = (const char*)(g_bf + (size_t)colBase * D);

    // prologue: issue chunk0 of first tile into stage 0 (overlaps cdf build)
    #pragma unroll
    for (int it = 0; it < 4; it++) {
        const int tile = it >> 1;
        int r = ((it & 1) << 6) + ldr;
        uint32_t dst = tilesBase + tile * 16384 + r * 128 + ((ldp ^ (r & 7)) << 4);
        const char* src = (tile ? gB : gA) + ((size_t)r * D + ldp * 8) * 2;
        cp16(dst, src);
    }
    cp_commit();

    // ---- build cdf table locally (redundant per CTA) ----
    if (tid < NB) scan[tid] = g_histpos[tid];
    __syncthreads();
    for (int off = 1; off < NB; off <<= 1) {
        float v = 0.0f;
        if (tid < NB && tid >= off) v = scan[tid - off];
        __syncthreads();
        if (tid < NB && tid >= off) scan[tid] += v;
        __syncthreads();
    }
    if (tid < NB) {
        float invP = 1.0f / scan[NB - 1];
        float d = (tid < NB - 1) ? g_histpos[tid + 1] * invP : 0.0f;
        cdfS[tid] = make_float2(scan[tid] * invP, d);
    }
    // scan[NB-1] (= P_pos) stays untouched below OFF_TILES for the final CTA.

    float accAll = 0.0f, accPos = 0.0f;

    while (tileIdx < NTILES) {
        int nextTile = tileIdx + NWORK;
        int rowBaseN = 0, colBaseN = 0;
        const char *gAn = gA, *gBn = gB;
        if (nextTile < NTILES) {
            decode_tile(nextTile, rowBaseN, colBaseN);
            gAn = (const char*)(g_bf + (size_t)rowBaseN * D);
            gBn = (const char*)(g_bf + (size_t)colBaseN * D);
        }

        __syncthreads();   // prior epilogue done reading clsS; cdfS visible
        if (tid < 128) clsS[tid] = classes[rowBase + tid];
        else if (tid < 256) clsS[tid] = classes[colBase + tid - 128];

        float acc[2][4][4];
        #pragma unroll
        for (int mi = 0; mi < 2; mi++)
            #pragma unroll
            for (int ni = 0; ni < 4; ni++)
                #pragma unroll
                for (int q = 0; q < 4; q++) acc[mi][ni][q] = 0.0f;

        for (int c = 0; c < NCHUNK; c++) {
            cp_wait0();
            __syncthreads();
            if (c + 1 < NCHUNK) {
                uint32_t stb = tilesBase + ((c + 1) & 1) * STAGE_BYTES;
                #pragma unroll
                for (int it = 0; it < 4; it++) {
                    const int tile = it >> 1;
                    int r = ((it & 1) << 6) + ldr;
                    uint32_t dst = stb + tile * 16384 + r * 128 + ((ldp ^ (r & 7)) << 4);
                    const char* src = (tile ? gB : gA) +
                                      ((size_t)r * D + (size_t)(c + 1) * BK + ldp * 8) * 2;
                    cp16(dst, src);
                }
            } else if (nextTile < NTILES) {
                #pragma unroll
                for (int it = 0; it < 4; it++) {
                    const int tile = it >> 1;
                    int r = ((it & 1) << 6) + ldr;
                    uint32_t dst = tilesBase + tile * 16384 + r * 128 + ((ldp ^ (r & 7)) << 4);
                    const char* src = (tile ? gBn : gAn) + ((size_t)r * D + ldp * 8) * 2;
                    cp16(dst, src);
                }
            }
            cp_commit();

            uint32_t aBase = tilesBase + (c & 1) * STAGE_BYTES;
            uint32_t bBase = aBase + 16384;

            #pragma unroll
            for (int ks = 0; ks < 4; ks++) {
                uint32_t af[2][4], bfr[4][2];
                #pragma unroll
                for (int mi = 0; mi < 2; mi++) {
                    int row = wm * 32 + mi * 16 + ((blk & 1) << 3) + lrow;
                    int piece = ks * 2 + (blk >> 1);
                    ldmx4(af[mi], aBase + row * 128 + ((piece ^ (row & 7)) << 4));
                }
                #pragma unroll
                for (int ni2 = 0; ni2 < 2; ni2++) {
                    int row = wn * 32 + ni2 * 16 + ((blk >> 1) << 3) + lrow;
                    int piece = ks * 2 + (blk & 1);
                    uint32_t r4[4];
                    ldmx4(r4, bBase + row * 128 + ((piece ^ (row & 7)) << 4));
                    bfr[ni2 * 2][0] = r4[0]; bfr[ni2 * 2][1] = r4[1];
                    bfr[ni2 * 2 + 1][0] = r4[2]; bfr[ni2 * 2 + 1][1] = r4[3];
                }
                #pragma unroll
                for (int mi = 0; mi < 2; mi++)
                    #pragma unroll
                    for (int ni = 0; ni < 4; ni++)
                        mma16816(acc[mi][ni], af[mi], bfr[ni]);
            }
        }

        // ---- fused epilogue: cdf lerp, pure register accumulation ----
        int iBase = rowBase + wm * 32 + (lane >> 2);
        int jBase = colBase + wn * 32 + (lane & 3) * 2;
        const int* clsB = clsS + 128;
        bool offDiag = (rowBase != colBase);

        #pragma unroll
        for (int mi = 0; mi < 2; mi++) {
            int i0 = iBase + mi * 16;
            int ci0 = clsS[i0 - rowBase];
            int ci1 = clsS[i0 + 8 - rowBase];
            #pragma unroll
            for (int ni = 0; ni < 4; ni++) {
                int j0 = jBase + ni * 8;
                int cj0 = clsB[j0 - colBase];
                int cj1 = clsB[j0 + 1 - colBase];
                #pragma unroll
                for (int q = 0; q < 4; q++) {
                    int i = i0 + ((q >> 1) << 3);
                    int j = j0 + (q & 1);
                    if (offDiag || i < j) {
                        int ci = (q & 2) ? ci1 : ci0;
                        int cj = (q & 1) ? cj1 : cj0;
                        float x = acc[mi][ni][q] * INV_STEP;
                        float kf = floorf(x);
                        float fr = x - kf;
                        int lo = (int)kf + HALFB;
                        if (lo < 0) { lo = 0; fr = 0.0f; }
                        else if (lo > NB - 2) { lo = NB - 2; fr = 1.0f; }
                        float2 cp = cdfS[lo];
                        float g = fmaf(fr, cp.y, cp.x);
                        accAll += g;
                        if (ci == cj) accPos += g;
                    }
                }
            }
        }

        tileIdx = nextTile;
        rowBase = rowBaseN; colBase = colBaseN;
        gA = gAn; gB = gBn;
    }

    // ---- CTA reduction of the two accumulators ----
    #pragma unroll
    for (int o = 16; o > 0; o >>= 1) {
        accAll += __shfl_xor_sync(0xffffffffu, accAll, o);
        accPos += __shfl_xor_sync(0xffffffffu, accPos, o);
    }
    float* redA = (float*)(smem + OFF_RED);
    float* redP = redA + 16;
    if (lane == 0) { redA[wid] = accAll; redP[wid] = accPos; }
    __syncthreads();
    if (tid == 0) {
        float sA = 0.0f, sP = 0.0f;
        #pragma unroll
        for (int w = 0; w < 16; w++) { sA += redA[w]; sP += redP[w]; }
        atomicAdd(&g_sumAll, (double)sA);
        atomicAdd(&g_sumPos, (double)sP);
    }

    // ---- last CTA writes the loss ----
    __threadfence();
    __shared__ int isLast;
    if (tid == 0) {
        int old = atomicAdd(&g_done, 1);
        isLast = (old == NWORK - 1) ? 1 : 0;
    }
    __syncthreads();
    if (isLast && tid == 0) {
        double Pp = (double)scan[NB - 1];
        double Pn = P_TOTAL - Pp;
        out[0] = (float)((g_sumAll - g_sumPos) / Pn);
    }
}

// ---------------------------------------------------------------------------
extern "C" void kernel_launch(void* const* d_in, const int* in_sizes, int n_in,
                              void* d_out, int out_size) {
    const float* features = (const float*)d_in[0];
    const int*   classes  = (const int*)d_in[1];
    float*       out      = (float*)d_out;

    cudaFuncSetAttribute(pair_mma_loss_kernel,
                         cudaFuncAttributeMaxDynamicSharedMemorySize, SMEM_TOTAL);

    norm_kernel<<<512, 256>>>(features);
    pos_kernel<<<128, 256>>>(classes);
    pair_mma_loss_kernel<<<NWORK, 512, SMEM_TOTAL>>>(classes, out);
}

// round 17
// speedup vs baseline: 1.1702x; 1.1268x over previous
#include <cuda_runtime.h>
#include <cuda_bf16.h>
#include <cstdint>
#include <math.h>

// ---------------------------------------------------------------------------
// Problem constants
// ---------------------------------------------------------------------------
#define N 4096
#define D 512
#define NB 151
#define HALFB 75
#define INV_STEP 75.0f
#define P_TOTAL 8386560.0   // N*(N-1)/2

#define BM 128
#define BK 64
#define NCHUNK (D / BK)     // 8
#define NT (N / BM)         // 32
#define NTILES (NT * (NT + 1) / 2)  // 528
#define NWORK 296           // 2 persistent CTAs per SM (all co-resident)
#define STAGE_BYTES 32768

// dynamic smem layout
#define OFF_CLS   0                 // 256 ints
#define OFF_CDF   1024              // 151 float2
#define OFF_RED   2240              // 32 floats
#define OFF_SCAN  2368              // 152 floats
#define OFF_TILES 4096              // tile stages; also classes cache in phase 2
#define SMEM_TOTAL (OFF_TILES + 2 * STAGE_BYTES)   // 69632

// ---------------------------------------------------------------------------
// Inline PTX helpers
// ---------------------------------------------------------------------------
__device__ __forceinline__ uint32_t smem_u32(const void* p) {
    uint32_t a;
    asm("{ .reg .u64 t; cvta.to.shared.u64 t, %1; cvt.u32.u64 %0, t; }" : "=r"(a) : "l"(p));
    return a;
}
__device__ __forceinline__ void cp16(uint32_t dst, const void* src) {
    asm volatile("cp.async.cg.shared.global [%0], [%1], 16;" :: "r"(dst), "l"(src) : "memory");
}
__device__ __forceinline__ void cp_commit() {
    asm volatile("cp.async.commit_group;" ::: "memory");
}
__device__ __forceinline__ void cp_wait0() {
    asm volatile("cp.async.wait_group 0;" ::: "memory");
}
__device__ __forceinline__ void ldmx4(uint32_t* r, uint32_t addr) {
    asm volatile("ldmatrix.sync.aligned.m8n8.x4.shared.b16 {%0,%1,%2,%3}, [%4];"
                 : "=r"(r[0]), "=r"(r[1]), "=r"(r[2]), "=r"(r[3]) : "r"(addr));
}
__device__ __forceinline__ void mma16816(float* c, const uint32_t* a, const uint32_t* b) {
    asm volatile("mma.sync.aligned.m16n8k16.row.col.f32.bf16.bf16.f32 "
                 "{%0,%1,%2,%3}, {%4,%5,%6,%7}, {%8,%9}, {%0,%1,%2,%3};"
                 : "+f"(c[0]), "+f"(c[1]), "+f"(c[2]), "+f"(c[3])
                 : "r"(a[0]), "r"(a[1]), "r"(a[2]), "r"(a[3]), "r"(b[0]), "r"(b[1]));
}

// ---------------------------------------------------------------------------
// Scratch (static device memory -- no allocations)
// ---------------------------------------------------------------------------
__device__ __nv_bfloat16 g_bf[(size_t)N * D];
__device__ float g_histpos[NB + 1];
__device__ double g_sumAll;
__device__ double g_sumPos;
__device__ int g_done;
__device__ unsigned g_barCount[2];
__device__ unsigned g_barPhase[2];

// device-wide sense-reversing barrier (all NWORK CTAs are co-resident)
__device__ __forceinline__ void grid_barrier(int k) {
    __syncthreads();
    if (threadIdx.x == 0) {
        __threadfence();
        unsigned p = g_barPhase[k];
        if (atomicAdd(&g_barCount[k], 1u) == NWORK - 1) {
            g_barCount[k] = 0;
            __threadfence();
            atomicExch(&g_barPhase[k], p + 1);
        } else {
            while (*(volatile unsigned*)&g_barPhase[k] == p) { }
        }
        __threadfence();
    }
    __syncthreads();
}

__device__ __forceinline__ float dot8(uint4 a, uint4 b) {
    unsigned av[4] = {a.x, a.y, a.z, a.w};
    unsigned bv[4] = {b.x, b.y, b.z, b.w};
    float s = 0.0f;
    #pragma unroll
    for (int r = 0; r < 4; r++) {
        float2 fa = __bfloat1622float2(*(__nv_bfloat162*)&av[r]);
        float2 fb = __bfloat1622float2(*(__nv_bfloat162*)&bv[r]);
        s = fmaf(fa.x, fb.x, s);
        s = fmaf(fa.y, fb.y, s);
    }
    return s;
}

__device__ __forceinline__ void decode_tile(int t, int& rowBase, int& colBase) {
    int br = 0;
    while (t >= NT - br) { t -= NT - br; br++; }
    rowBase = br * BM;
    colBase = (br + t) * BM;
}

// ---------------------------------------------------------------------------
// Fused persistent kernel: norm -> barrier -> pos -> barrier -> cdf + GEMM
// ---------------------------------------------------------------------------
__global__ void __launch_bounds__(512, 2) fused_kernel(
        const float* __restrict__ features,
        const int* __restrict__ classes,
        float* __restrict__ out) {
    extern __shared__ char smem[];
    uint32_t sb = smem_u32(smem);
    int tid = threadIdx.x;
    int wid = tid >> 5;
    int lane = tid & 31;

    int* clsS = (int*)(smem + OFF_CLS);
    float2* cdfS = (float2*)(smem + OFF_CDF);
    float* scan = (float*)(smem + OFF_SCAN);
    uint32_t tilesBase = sb + OFF_TILES;

    // ---------------- phase 1: reset state + L2-normalize ----------------
    if (blockIdx.x == 0) {
        if (tid == 0) { g_sumAll = 0.0; g_sumPos = 0.0; g_done = 0; }
        if (tid < NB + 1) g_histpos[tid] = 0.0f;
    }
    {
        int row = blockIdx.x * 16 + wid;
        if (row < N) {
            const float4* src = (const float4*)(features + (size_t)row * D);
            float4 v[4];
            float ss = 0.0f;
            #pragma unroll
            for (int r = 0; r < 4; r++) {
                v[r] = src[lane + 32 * r];
                ss += v[r].x * v[r].x + v[r].y * v[r].y + v[r].z * v[r].z + v[r].w * v[r].w;
            }
            #pragma unroll
            for (int o = 16; o > 0; o >>= 1) ss += __shfl_xor_sync(0xffffffffu, ss, o);
            float inv = 1.0f / sqrtf(ss);
            uint2* dst = (uint2*)(g_bf + (size_t)row * D);
            #pragma unroll
            for (int r = 0; r < 4; r++) {
                __nv_bfloat162 p0 = __floats2bfloat162_rn(v[r].x * inv, v[r].y * inv);
                __nv_bfloat162 p1 = __floats2bfloat162_rn(v[r].z * inv, v[r].w * inv);
                dst[lane + 32 * r] = make_uint2(*(unsigned*)&p0, *(unsigned*)&p1);
            }
        }
    }
    grid_barrier(0);

    // ---------------- phase 2: positive pairs (classes cached in smem) ----
    {
        int* clsCache = (int*)(smem + OFF_TILES);   // 4096 ints = 16KB
        for (int k = tid; k < N; k += 512) clsCache[k] = classes[k];
        __syncthreads();
        int i = blockIdx.x * 16 + wid;
        if (i < N) {
            int ci = clsCache[i];
            const uint4* ri = (const uint4*)(g_bf + (size_t)i * D);
            uint4 a0 = ri[lane];
            uint4 a1 = ri[lane + 32];
            for (int jb = i + 1; jb < N; jb += 32) {
                int j = jb + lane;
                bool m = (j < N) && (clsCache[j] == ci);
                unsigned mm = __ballot_sync(0xffffffffu, m);
                while (mm) {
                    int src = __ffs(mm) - 1;
                    mm &= mm - 1;
                    int jj = jb + src;
                    const uint4* rj = (const uint4*)(g_bf + (size_t)jj * D);
                    float s = dot8(a0, rj[lane]) + dot8(a1, rj[lane + 32]);
                    #pragma unroll
                    for (int o = 16; o > 0; o >>= 1) s += __shfl_xor_sync(0xffffffffu, s, o);
                    if (lane == 0) {
                        float x = s * INV_STEP;
                        float kf = floorf(x);
                        float fr = x - kf;
                        int lo = (int)kf + HALFB;
                        if (lo < 0) { lo = 0; fr = 0.0f; }
                        else if (lo > NB - 2) { lo = NB - 2; fr = 1.0f; }
                        atomicAdd(&g_histpos[lo], 1.0f - fr);
                        atomicAdd(&g_histpos[lo + 1], fr);
                    }
                }
            }
        }
        __syncthreads();   // CTA done reading clsCache; tile region reusable
    }

    // GEMM setup + chunk-0 prefetch (overlaps the barrier wait below)
    int ldr = tid >> 3;
    int ldp = tid & 7;
    int wm = wid & 3;
    int wn = wid >> 2;
    int blk = lane >> 3;
    int lrow = lane & 7;

    int tileIdx = blockIdx.x;
    int rowBase, colBase;
    decode_tile(tileIdx, rowBase, colBase);
    const char* gA = (const char*)(g_bf + (size_t)rowBase * D);
    const char* gB = (const char*)(g_bf + (size_t)colBase * D);

    #pragma unroll
    for (int it = 0; it < 4; it++) {
        const int tile = it >> 1;
        int r = ((it & 1) << 6) + ldr;
        uint32_t dst = tilesBase + tile * 16384 + r * 128 + ((ldp ^ (r & 7)) << 4);
        const char* src = (tile ? gB : gA) + ((size_t)r * D + ldp * 8) * 2;
        cp16(dst, src);
    }
    cp_commit();

    grid_barrier(1);   // g_histpos complete everywhere

    // ---------------- phase 3: per-CTA cdf build ----------------
    if (tid < NB) scan[tid] = g_histpos[tid];
    __syncthreads();
    for (int off = 1; off < NB; off <<= 1) {
        float v = 0.0f;
        if (tid < NB && tid >= off) v = scan[tid - off];
        __syncthreads();
        if (tid < NB && tid >= off) scan[tid] += v;
        __syncthreads();
    }
    if (tid < NB) {
        float invP = 1.0f / scan[NB - 1];
        float d = (tid < NB - 1) ? g_histpos[tid + 1] * invP : 0.0f;
        cdfS[tid] = make_float2(scan[tid] * invP, d);
    }

    // ---------------- phase 4: persistent HMMA GEMM + lerp epilogue -------
    float accAll = 0.0f, accPos = 0.0f;

    while (tileIdx < NTILES) {
        int nextTile = tileIdx + NWORK;
        int rowBaseN = 0, colBaseN = 0;
        const char *gAn = gA, *gBn = gB;
        if (nextTile < NTILES) {
            decode_tile(nextTile, rowBaseN, colBaseN);
            gAn = (const char*)(g_bf + (size_t)rowBaseN * D);
            gBn = (const char*)(g_bf + (size_t)colBaseN * D);
        }

        __syncthreads();
        if (tid < 128) clsS[tid] = classes[rowBase + tid];
        else if (tid < 256) clsS[tid] = classes[colBase + tid - 128];

        float acc[2][4][4];
        #pragma unroll
        for (int mi = 0; mi < 2; mi++)
            #pragma unroll
            for (int ni = 0; ni < 4; ni++)
                #pragma unroll
                for (int q = 0; q < 4; q++) acc[mi][ni][q] = 0.0f;

        for (int c = 0; c < NCHUNK; c++) {
            cp_wait0();
            __syncthreads();
            if (c + 1 < NCHUNK) {
                uint32_t stb = tilesBase + ((c + 1) & 1) * STAGE_BYTES;
                #pragma unroll
                for (int it = 0; it < 4; it++) {
                    const int tile = it >> 1;
                    int r = ((it & 1) << 6) + ldr;
                    uint32_t dst = stb + tile * 16384 + r * 128 + ((ldp ^ (r & 7)) << 4);
                    const char* src = (tile ? gB : gA) +
                                      ((size_t)r * D + (size_t)(c + 1) * BK + ldp * 8) * 2;
                    cp16(dst, src);
                }
            } else if (nextTile < NTILES) {
                #pragma unroll
                for (int it = 0; it < 4; it++) {
                    const int tile = it >> 1;
                    int r = ((it & 1) << 6) + ldr;
                    uint32_t dst = tilesBase + tile * 16384 + r * 128 + ((ldp ^ (r & 7)) << 4);
                    const char* src = (tile ? gBn : gAn) + ((size_t)r * D + ldp * 8) * 2;
                    cp16(dst, src);
                }
            }
            cp_commit();

            uint32_t aBase = tilesBase + (c & 1) * STAGE_BYTES;
            uint32_t bBase = aBase + 16384;

            #pragma unroll
            for (int ks = 0; ks < 4; ks++) {
                uint32_t af[2][4], bfr[4][2];
                #pragma unroll
                for (int mi = 0; mi < 2; mi++) {
                    int row = wm * 32 + mi * 16 + ((blk & 1) << 3) + lrow;
                    int piece = ks * 2 + (blk >> 1);
                    ldmx4(af[mi], aBase + row * 128 + ((piece ^ (row & 7)) << 4));
                }
                #pragma unroll
                for (int ni2 = 0; ni2 < 2; ni2++) {
                    int row = wn * 32 + ni2 * 16 + ((blk >> 1) << 3) + lrow;
                    int piece = ks * 2 + (blk & 1);
                    uint32_t r4[4];
                    ldmx4(r4, bBase + row * 128 + ((piece ^ (row & 7)) << 4));
                    bfr[ni2 * 2][0] = r4[0]; bfr[ni2 * 2][1] = r4[1];
                    bfr[ni2 * 2 + 1][0] = r4[2]; bfr[ni2 * 2 + 1][1] = r4[3];
                }
                #pragma unroll
                for (int mi = 0; mi < 2; mi++)
                    #pragma unroll
                    for (int ni = 0; ni < 4; ni++)
                        mma16816(acc[mi][ni], af[mi], bfr[ni]);
            }
        }

        // ---- fused epilogue: cdf lerp, register accumulation ----
        int iBase = rowBase + wm * 32 + (lane >> 2);
        int jBase = colBase + wn * 32 + (lane & 3) * 2;
        const int* clsB = clsS + 128;
        bool offDiag = (rowBase != colBase);

        if (offDiag) {
            #pragma unroll
            for (int mi = 0; mi < 2; mi++) {
                int i0 = iBase + mi * 16;
                int ci0 = clsS[i0 - rowBase];
                int ci1 = clsS[i0 + 8 - rowBase];
                #pragma unroll
                for (int ni = 0; ni < 4; ni++) {
                    int j0 = jBase + ni * 8;
                    int cj0 = clsB[j0 - colBase];
                    int cj1 = clsB[j0 + 1 - colBase];
                    #pragma unroll
                    for (int q = 0; q < 4; q++) {
                        int ci = (q & 2) ? ci1 : ci0;
                        int cj = (q & 1) ? cj1 : cj0;
                        float x = fmaf(acc[mi][ni][q], INV_STEP, (float)HALFB);
                        float kf = floorf(x);
                        float fr = x - kf;
                        int lo = min(max((int)kf, 0), NB - 2);
                        float2 cp = cdfS[lo];
                        float g = fmaf(fr, cp.y, cp.x);
                        accAll += g;
                        if (ci == cj) accPos += g;
                    }
                }
            }
        } else {
            #pragma unroll
            for (int mi = 0; mi < 2; mi++) {
                int i0 = iBase + mi * 16;
                int ci0 = clsS[i0 - rowBase];
                int ci1 = clsS[i0 + 8 - rowBase];
                #pragma unroll
                for (int ni = 0; ni < 4; ni++) {
                    int j0 = jBase + ni * 8;
                    int cj0 = clsB[j0 - colBase];
                    int cj1 = clsB[j0 + 1 - colBase];
                    #pragma unroll
                    for (int q = 0; q < 4; q++) {
                        int i = i0 + ((q >> 1) << 3);
                        int j = j0 + (q & 1);
                        if (i < j) {
                            int ci = (q & 2) ? ci1 : ci0;
                            int cj = (q & 1) ? cj1 : cj0;
                            float x = fmaf(acc[mi][ni][q], INV_STEP, (float)HALFB);
                            float kf = floorf(x);
                            float fr = x - kf;
                            int lo = min(max((int)kf, 0), NB - 2);
                            float2 cp = cdfS[lo];
                            float g = fmaf(fr, cp.y, cp.x);
                            accAll += g;
                            if (ci == cj) accPos += g;
                        }
                    }
                }
            }
        }

        tileIdx = nextTile;
        rowBase = rowBaseN; colBase = colBaseN;
        gA = gAn; gB = gBn;
    }

    // ---- CTA reduction + global accumulate ----
    #pragma unroll
    for (int o = 16; o > 0; o >>= 1) {
        accAll += __shfl_xor_sync(0xffffffffu, accAll, o);
        accPos += __shfl_xor_sync(0xffffffffu, accPos, o);
    }
    float* redA = (float*)(smem + OFF_RED);
    float* redP = redA + 16;
    if (lane == 0) { redA[wid] = accAll; redP[wid] = accPos; }
    __syncthreads();
    if (tid == 0) {
        float sA = 0.0f, sP = 0.0f;
        #pragma unroll
        for (int w = 0; w < 16; w++) { sA += redA[w]; sP += redP[w]; }
        atomicAdd(&g_sumAll, (double)sA);
        atomicAdd(&g_sumPos, (double)sP);
    }

    // ---- last CTA writes the loss ----
    __threadfence();
    __shared__ int isLast;
    if (tid == 0) {
        int old = atomicAdd(&g_done, 1);
        isLast = (old == NWORK - 1) ? 1 : 0;
    }
    __syncthreads();
    if (isLast && tid == 0) {
        double Pp = (double)scan[NB - 1];
        double Pn = P_TOTAL - Pp;
        out[0] = (float)((g_sumAll - g_sumPos) / Pn);
    }
}

// ---------------------------------------------------------------------------
extern "C" void kernel_launch(void* const* d_in, const int* in_sizes, int n_in,
                              void* d_out, int out_size) {
    const float* features = (const float*)d_in[0];
    const int*   classes  = (const int*)d_in[1];
    float*       out      = (float*)d_out;

    cudaFuncSetAttribute(fused_kernel,
                         cudaFuncAttributeMaxDynamicSharedMemorySize, SMEM_TOTAL);

    fused_kernel<<<NWORK, 512, SMEM_TOTAL>>>(features, classes, out);
}